// round 3
// baseline (speedup 1.0000x reference)
#include <cuda_runtime.h>

#define NUM_NODE 150
#define FEAT 4
#define ROWF (NUM_NODE * FEAT)   // 600 floats per row
#define RPW 4                    // rows per warp

__global__ __launch_bounds__(256)
void obstacle_lane_kernel(const float* __restrict__ lf,
                          const float2* __restrict__ obs_pos,
                          const int* __restrict__ mask,
                          float* __restrict__ out,
                          int M)
{
    int warp = (blockIdx.x * blockDim.x + threadIdx.x) >> 5;
    int lane = threadIdx.x & 31;

    int base = RPW * warp;
    if (base >= M) return;

    // row indices, clamped (duplicate rows write identical values -> benign)
    int r0 = base;
    int r1 = min(base + 1, M - 1);
    int r2 = min(base + 2, M - 1);
    int r3 = min(base + 3, M - 1);

    const float* row0 = lf + (long)r0 * ROWF;
    const float* row1 = lf + (long)r1 * ROWF;
    const float* row2 = lf + (long)r2 * ROWF;
    const float* row3 = lf + (long)r3 * ROWF;

    // rep points (mask sorted -> hot in cache)
    float2 rp0 = __ldg(obs_pos + __ldg(mask + r0));
    float2 rp1 = __ldg(obs_pos + __ldg(mask + r1));
    float2 rp2 = __ldg(obs_pos + __ldg(mask + r2));
    float2 rp3 = __ldg(obs_pos + __ldg(mask + r3));

    // lane's node indices: 1+lane, 33+lane, 65+lane, 97+lane, min(129+lane,148)
    int i4 = min(129 + lane, 148);
    int o0 = 4 * (1 + lane);
    int o4 = 4 * i4;

    // ---- front-batched: 20 independent streaming loads in flight ----
    float2 a0 = __ldcs((const float2*)(row0 + o0));
    float2 a1 = __ldcs((const float2*)(row0 + o0 + 128));
    float2 a2 = __ldcs((const float2*)(row0 + o0 + 256));
    float2 a3 = __ldcs((const float2*)(row0 + o0 + 384));
    float2 a4 = __ldcs((const float2*)(row0 + o4));
    float2 b0 = __ldcs((const float2*)(row1 + o0));
    float2 b1 = __ldcs((const float2*)(row1 + o0 + 128));
    float2 b2 = __ldcs((const float2*)(row1 + o0 + 256));
    float2 b3 = __ldcs((const float2*)(row1 + o0 + 384));
    float2 b4 = __ldcs((const float2*)(row1 + o4));
    float2 c0 = __ldcs((const float2*)(row2 + o0));
    float2 c1 = __ldcs((const float2*)(row2 + o0 + 128));
    float2 c2 = __ldcs((const float2*)(row2 + o0 + 256));
    float2 c3 = __ldcs((const float2*)(row2 + o0 + 384));
    float2 c4 = __ldcs((const float2*)(row2 + o4));
    float2 e0 = __ldcs((const float2*)(row3 + o0));
    float2 e1 = __ldcs((const float2*)(row3 + o0 + 128));
    float2 e2 = __ldcs((const float2*)(row3 + o0 + 256));
    float2 e3 = __ldcs((const float2*)(row3 + o0 + 384));
    float2 e4 = __ldcs((const float2*)(row3 + o4));

#define DIST(v, rp) ((v.x - rp.x) * (v.x - rp.x) + (v.y - rp.y) * (v.y - rp.y))
#define STEP(v, rp, best, bidx, idx) { float _d = DIST(v, rp); if (_d < best) { best = _d; bidx = idx; } }

    // ---- four interleaved argmin chains ----
    float best0 = DIST(a0, rp0); int bidx0 = 1 + lane;
    float best1 = DIST(b0, rp1); int bidx1 = 1 + lane;
    float best2 = DIST(c0, rp2); int bidx2 = 1 + lane;
    float best3 = DIST(e0, rp3); int bidx3 = 1 + lane;

    STEP(a1, rp0, best0, bidx0, 33 + lane); STEP(b1, rp1, best1, bidx1, 33 + lane);
    STEP(c1, rp2, best2, bidx2, 33 + lane); STEP(e1, rp3, best3, bidx3, 33 + lane);
    STEP(a2, rp0, best0, bidx0, 65 + lane); STEP(b2, rp1, best1, bidx1, 65 + lane);
    STEP(c2, rp2, best2, bidx2, 65 + lane); STEP(e2, rp3, best3, bidx3, 65 + lane);
    STEP(a3, rp0, best0, bidx0, 97 + lane); STEP(b3, rp1, best1, bidx1, 97 + lane);
    STEP(c3, rp2, best2, bidx2, 97 + lane); STEP(e3, rp3, best3, bidx3, 97 + lane);
    STEP(a4, rp0, best0, bidx0, i4);        STEP(b4, rp1, best1, bidx1, i4);
    STEP(c4, rp2, best2, bidx2, i4);        STEP(e4, rp3, best3, bidx3, i4);

    // ---- butterfly min (all rows overlapped), then min-index among minima ----
    float m0 = best0, m1 = best1, m2 = best2, m3 = best3;
#pragma unroll
    for (int off = 16; off > 0; off >>= 1) {
        m0 = fminf(m0, __shfl_xor_sync(0xffffffffu, m0, off));
        m1 = fminf(m1, __shfl_xor_sync(0xffffffffu, m1, off));
        m2 = fminf(m2, __shfl_xor_sync(0xffffffffu, m2, off));
        m3 = fminf(m3, __shfl_xor_sync(0xffffffffu, m3, off));
    }
    int gi0 = (int)__reduce_min_sync(0xffffffffu, (best0 == m0) ? (unsigned)bidx0 : 0x7fffffffu);
    int gi1 = (int)__reduce_min_sync(0xffffffffu, (best1 == m1) ? (unsigned)bidx1 : 0x7fffffffu);
    int gi2 = (int)__reduce_min_sync(0xffffffffu, (best2 == m2) ? (unsigned)bidx2 : 0x7fffffffu);
    int gi3 = (int)__reduce_min_sync(0xffffffffu, (best3 == m3) ? (unsigned)bidx3 : 0x7fffffffu);

    // ---- epilogues for 4 rows run concurrently on lanes 0..3 ----
    if (lane < 4) {
        int r; int bi; float2 rp; const float* row;
        if      (lane == 0) { r = r0; bi = gi0; rp = rp0; row = row0; }
        else if (lane == 1) { r = r1; bi = gi1; rp = rp1; row = row1; }
        else if (lane == 2) { r = r2; bi = gi2; rp = rp2; row = row2; }
        else                { r = r3; bi = gi3; rp = rp3; row = row3; }

        float4 mn = *reinterpret_cast<const float4*>(row + 4 * bi);
        float4 pv = *reinterpret_cast<const float4*>(row + 4 * (bi - 1));
        float4 nx = *reinterpret_cast<const float4*>(row + 4 * (bi + 1));

        float dpx = pv.x - mn.x, dpy = pv.y - mn.y, dpz = pv.z - mn.z, dpw = pv.w - mn.w;
        float dnx = nx.x - mn.x, dny = nx.y - mn.y, dnz = nx.z - mn.z, dnw = nx.w - mn.w;
        float dist_prev = dpx*dpx + dpy*dpy + dpz*dpz + dpw*dpw;
        float dist_next = dnx*dnx + dny*dny + dnz*dnz + dnw*dnw;

        int before, after;
        float sx, sy, ex, ey;
        if (dist_next < dist_prev) {
            before = bi;     after = bi + 1;
            sx = mn.x; sy = mn.y; ex = nx.x; ey = nx.y;
        } else {
            before = bi - 1; after = bi;
            sx = pv.x; sy = pv.y; ex = mn.x; ey = mn.y;
        }

        float lvx = ex - sx, lvy = ey - sy;
        float mag = sqrtf(lvx * lvx + lvy * lvy);
        float ux = lvx / mag, uy = lvy / mag;
        float pm = (rp.x - sx) * ux + (rp.y - sy) * uy;

        // output layout: [proj_pt (M,2) | indices (M,2) | rep (M,2)] flattened f32
        long o1 = 2L * M;
        long o2 = 4L * M;
        out[2 * r + 0]      = sx + pm * ux;
        out[2 * r + 1]      = sy + pm * uy;
        out[o1 + 2 * r + 0] = (float)before;
        out[o1 + 2 * r + 1] = (float)after;
        out[o2 + 2 * r + 0] = rp.x;
        out[o2 + 2 * r + 1] = rp.y;
    }
}

extern "C" void kernel_launch(void* const* d_in, const int* in_sizes, int n_in,
                              void* d_out, int out_size)
{
    const float*  lf      = (const float*)d_in[0];   // (M, 150, 4) f32
    const float2* obs_pos = (const float2*)d_in[1];  // (N, 2) f32
    const int*    mask    = (const int*)d_in[2];     // (M, 1) i32
    float* out = (float*)d_out;

    int M = in_sizes[0] / ROWF;

    const int threads = 256;             // 8 warps/block, 4 rows/warp = 32 rows/block
    int warps_needed = (M + RPW - 1) / RPW;
    int blocks = (warps_needed + 7) / 8;
    obstacle_lane_kernel<<<blocks, threads>>>(lf, obs_pos, mask, out, M);
}